// round 4
// baseline (speedup 1.0000x reference)
#include <cuda_runtime.h>
#include <math_constants.h>
#include <cstdint>

#define Bb 16
#define Ss 2048
#define Hh 1024
#define Mm (Bb * Ss)   // 32768

__device__ float g_q[Bb * Hh];
__device__ float g_ctx_part[16 * 32 * 1024];

// ---------------------------------------------------------------- helpers
__device__ __forceinline__ uint32_t smem_u32(const void* p) {
    uint32_t a;
    asm("{ .reg .u64 t; cvta.to.shared.u64 t, %1; cvt.u32.u64 %0, t; }" : "=r"(a) : "l"(p));
    return a;
}
__device__ __forceinline__ uint32_t f2tf(float f) {
    uint32_t u; asm("cvt.rna.tf32.f32 %0, %1;" : "=r"(u) : "f"(f)); return u;
}
__device__ __forceinline__ void cp_async16(uint32_t dst, const void* src) {
    asm volatile("cp.async.cg.shared.global [%0], [%1], 16;" :: "r"(dst), "l"(src));
}
__device__ __forceinline__ void cp_commit() { asm volatile("cp.async.commit_group;"); }
__device__ __forceinline__ void cp_wait1()  { asm volatile("cp.async.wait_group 1;"); }
__device__ __forceinline__ void cp_wait0()  { asm volatile("cp.async.wait_group 0;"); }

__device__ __forceinline__ void mma_tf32(float* d, const uint32_t* a, const uint32_t* b) {
    asm volatile(
        "mma.sync.aligned.m16n8k8.row.col.f32.tf32.tf32.f32 "
        "{%0,%1,%2,%3}, {%4,%5,%6,%7}, {%8,%9}, {%0,%1,%2,%3};"
        : "+f"(d[0]), "+f"(d[1]), "+f"(d[2]), "+f"(d[3])
        : "r"(a[0]), "r"(a[1]), "r"(a[2]), "r"(a[3]), "r"(b[0]), "r"(b[1]));
}

// ---------------------------------------------------------------------------
// Kernel 0: zero the scores region (d_out is poisoned)
// ---------------------------------------------------------------------------
__global__ void zero_scores(float* __restrict__ s) {
    s[blockIdx.x * 1024 + threadIdx.x] = 0.f;
}

// ---------------------------------------------------------------------------
// Kernel 1: q[b,o] = dot(h[b,:], attn_W[o, 0:H]) + attn_b[o]
// ---------------------------------------------------------------------------
__global__ void q_kernel(const float* __restrict__ h,
                         const float* __restrict__ W,
                         const float* __restrict__ bias) {
    int b = blockIdx.x;
    __shared__ float hs[Hh];
    for (int i = threadIdx.x; i < Hh; i += blockDim.x) hs[i] = h[b * Hh + i];
    __syncthreads();
    int warp = threadIdx.x >> 5, lane = threadIdx.x & 31;
    int o = blockIdx.y * 8 + warp;
    const float* Wrow = W + (size_t)o * (2 * Hh);
    float acc = 0.f;
    #pragma unroll 8
    for (int k = lane; k < Hh; k += 32) acc += hs[k] * Wrow[k];
    #pragma unroll
    for (int off = 16; off; off >>= 1) acc += __shfl_xor_sync(0xffffffffu, acc, off);
    if (lane == 0) g_q[b * Hh + o] = acc + bias[o];
}

// ---------------------------------------------------------------------------
// Kernel 2: fused scores GEMM via tf32 mma.sync (m16n8k8).
// Grid (N/128, M/128) — bn FASTEST so one wave stays L2-resident on A.
// CTA tile 128x128, BK=16, 3-stage cp.async pipeline, ONE barrier per iter.
// Epilogue: relu(+q)*v row-reduction in registers, atomicAdd row partials.
// ---------------------------------------------------------------------------
#define BKI 16
#define PAD 20
#define NIT (Hh / BKI)   // 64
#define STG 3
#define TILE_F (128 * PAD)            // floats per matrix tile
#define STAGE_F (2 * TILE_F)          // floats per stage (A + B)
#define SC_SMEM (STG * STAGE_F * 4)   // 61440 bytes

__global__ void __launch_bounds__(256)
scores_mma(const float* __restrict__ A,
           const float* __restrict__ W,
           const float* __restrict__ v,
           float* __restrict__ out_scores) {
    extern __shared__ float sm[];
    __shared__ float s_q[128];
    __shared__ float s_v[128];

    const int tid  = threadIdx.x;
    const int wid  = tid >> 5, lane = tid & 31;
    const int g    = lane >> 2, t = lane & 3;
    const int bn   = blockIdx.x;          // n block (128 cols) — fastest
    const int bm   = blockIdx.y;          // m block (128 rows)
    const int b    = (bm * 128) >> 11;    // batch
    const int wm   = (wid & 3) * 32;      // warp m offset
    const int wn   = (wid >> 2) * 64;     // warp n offset

    if (tid < 128) {
        s_q[tid] = g_q[b * Hh + bn * 128 + tid];
        s_v[tid] = v[bn * 128 + tid];
    }

    const float* Agbase = A + (size_t)(bm * 128) * Hh;
    const float* Wgbase = W + (size_t)(bn * 128) * (2 * Hh) + Hh;

    const int r0 = tid >> 2, c0 = tid & 3;     // rows 0..63, float4 col
    const int r1 = r0 + 64;

    uint32_t aw[STG][2], bw[STG][2];
    #pragma unroll
    for (int s = 0; s < STG; s++) {
        uint32_t base = smem_u32(sm + s * STAGE_F);
        aw[s][0] = base + (r0 * PAD + c0 * 4) * 4;
        aw[s][1] = base + (r1 * PAD + c0 * 4) * 4;
        bw[s][0] = base + (TILE_F + r0 * PAD + c0 * 4) * 4;
        bw[s][1] = base + (TILE_F + r1 * PAD + c0 * 4) * 4;
    }

    auto load_stage = [&](int s, int k0) {
        cp_async16(aw[s][0], Agbase + (size_t)r0 * Hh + k0 + c0 * 4);
        cp_async16(aw[s][1], Agbase + (size_t)r1 * Hh + k0 + c0 * 4);
        cp_async16(bw[s][0], Wgbase + (size_t)r0 * (2 * Hh) + k0 + c0 * 4);
        cp_async16(bw[s][1], Wgbase + (size_t)r1 * (2 * Hh) + k0 + c0 * 4);
        cp_commit();
    };

    float acc[2][8][4] = {};

    load_stage(0, 0);
    load_stage(1, BKI);

    for (int it = 0; it < NIT; it++) {
        const int buf = it % STG;
        if (it == NIT - 1) cp_wait0(); else cp_wait1();
        __syncthreads();                       // stage `it` visible; compute(it-1) done everywhere
        if (it + 2 < NIT) load_stage((it + 2) % STG, (it + 2) * BKI);

        const float* AsB = sm + buf * STAGE_F;
        const float* BsB = AsB + TILE_F;

        #pragma unroll
        for (int ks = 0; ks < 2; ks++) {
            const int kb = ks * 8;
            uint32_t af[2][4];
            #pragma unroll
            for (int i = 0; i < 2; i++) {
                const int mr = wm + i * 16;
                af[i][0] = f2tf(AsB[(mr + g    ) * PAD + kb + t    ]);
                af[i][1] = f2tf(AsB[(mr + g + 8) * PAD + kb + t    ]);
                af[i][2] = f2tf(AsB[(mr + g    ) * PAD + kb + t + 4]);
                af[i][3] = f2tf(AsB[(mr + g + 8) * PAD + kb + t + 4]);
            }
            #pragma unroll
            for (int j = 0; j < 8; j++) {
                uint32_t bf[2];
                bf[0] = f2tf(BsB[(wn + j * 8 + g) * PAD + kb + t    ]);
                bf[1] = f2tf(BsB[(wn + j * 8 + g) * PAD + kb + t + 4]);
                mma_tf32(acc[0][j], af[0], bf);
                mma_tf32(acc[1][j], af[1], bf);
            }
        }
    }

    // epilogue: relu(+q)*v, reduce cols
    float rs[2][2] = {};
    #pragma unroll
    for (int j = 0; j < 8; j++) {
        const int nl = wn + j * 8 + 2 * t;
        const float q0 = s_q[nl], q1 = s_q[nl + 1];
        const float v0 = s_v[nl], v1 = s_v[nl + 1];
        #pragma unroll
        for (int i = 0; i < 2; i++) {
            rs[i][0] += fmaxf(acc[i][j][0] + q0, 0.f) * v0 + fmaxf(acc[i][j][1] + q1, 0.f) * v1;
            rs[i][1] += fmaxf(acc[i][j][2] + q0, 0.f) * v0 + fmaxf(acc[i][j][3] + q1, 0.f) * v1;
        }
    }
    #pragma unroll
    for (int off = 1; off < 4; off <<= 1) {
        #pragma unroll
        for (int i = 0; i < 2; i++) {
            rs[i][0] += __shfl_xor_sync(0xffffffffu, rs[i][0], off);
            rs[i][1] += __shfl_xor_sync(0xffffffffu, rs[i][1], off);
        }
    }
    if (t == 0) {
        const int rowb = bm * 128 + wm;
        #pragma unroll
        for (int i = 0; i < 2; i++) {
            atomicAdd(&out_scores[rowb + i * 16 + g    ], rs[i][0]);
            atomicAdd(&out_scores[rowb + i * 16 + g + 8], rs[i][1]);
        }
    }
}

// ---------------------------------------------------------------------------
// Kernel 3: in-place softmax over S per batch
// ---------------------------------------------------------------------------
__global__ void softmax_kernel(float* __restrict__ w) {
    int b = blockIdx.x;
    float* row = w + (size_t)b * Ss;
    __shared__ float red[256];
    int tid = threadIdx.x;

    float m = -CUDART_INF_F;
    for (int i = tid; i < Ss; i += 256) m = fmaxf(m, row[i]);
    red[tid] = m; __syncthreads();
    for (int s = 128; s; s >>= 1) { if (tid < s) red[tid] = fmaxf(red[tid], red[tid + s]); __syncthreads(); }
    m = red[0]; __syncthreads();

    float sum = 0.f;
    for (int i = tid; i < Ss; i += 256) { float e = __expf(row[i] - m); row[i] = e; sum += e; }
    red[tid] = sum; __syncthreads();
    for (int s = 128; s; s >>= 1) { if (tid < s) red[tid] += red[tid + s]; __syncthreads(); }
    float inv = 1.f / red[0]; __syncthreads();
    for (int i = tid; i < Ss; i += 256) row[i] *= inv;
}

// ---------------------------------------------------------------------------
// Kernel 4a: context partials. grid (32 schunks, B), block 256; 64 rows/chunk
// ---------------------------------------------------------------------------
__global__ void context_part_kernel(const float* __restrict__ A,
                                    const float* __restrict__ w) {
    int sc = blockIdx.x, b = blockIdx.y;
    __shared__ float ws[64];
    int tid = threadIdx.x;
    if (tid < 64) ws[tid] = w[(size_t)b * Ss + sc * 64 + tid];
    __syncthreads();
    int h4 = tid * 4;
    const float* Ab = A + ((size_t)b * Ss + sc * 64) * Hh + h4;
    float4 acc = {0.f, 0.f, 0.f, 0.f};
    #pragma unroll 8
    for (int s = 0; s < 64; s++) {
        float4 av = __ldg((const float4*)(Ab + (size_t)s * Hh));
        float wv = ws[s];
        acc.x += wv * av.x; acc.y += wv * av.y; acc.z += wv * av.z; acc.w += wv * av.w;
    }
    *(float4*)(g_ctx_part + ((size_t)(b * 32 + sc) * Hh) + h4) = acc;
}

// Kernel 4b: reduce partials
__global__ void context_reduce_kernel(float* __restrict__ ctx) {
    int b = blockIdx.x;
    int h4 = threadIdx.x * 4;
    float4 s = {0.f, 0.f, 0.f, 0.f};
    #pragma unroll
    for (int j = 0; j < 32; j++) {
        float4 p = *(const float4*)(g_ctx_part + ((size_t)(b * 32 + j) * Hh) + h4);
        s.x += p.x; s.y += p.y; s.z += p.z; s.w += p.w;
    }
    *(float4*)(ctx + (size_t)b * Hh + h4) = s;
}

// ---------------------------------------------------------------------------
extern "C" void kernel_launch(void* const* d_in, const int* in_sizes, int n_in,
                              void* d_out, int out_size) {
    const float* h    = (const float*)d_in[0];
    // d_in[1] = c (unused)
    const float* a    = (const float*)d_in[2];
    const float* W    = (const float*)d_in[3];
    const float* bias = (const float*)d_in[4];
    const float* vW   = (const float*)d_in[5];

    float* ctx_out  = (float*)d_out;              // (B,1,H)
    float* attn_out = (float*)d_out + Bb * Hh;    // (B,S)

    static bool attr_set = false;
    if (!attr_set) {
        cudaFuncSetAttribute(scores_mma, cudaFuncAttributeMaxDynamicSharedMemorySize, SC_SMEM);
        attr_set = true;
    }

    zero_scores<<<Mm / 1024, 1024>>>(attn_out);
    q_kernel<<<dim3(Bb, Hh / 8), 256>>>(h, W, bias);
    scores_mma<<<dim3(Hh / 128, Mm / 128), 256, SC_SMEM>>>(a, W, vW, attn_out);
    softmax_kernel<<<Bb, 256>>>(attn_out);
    context_part_kernel<<<dim3(32, Bb), 256>>>(a, attn_out);
    context_reduce_kernel<<<Bb, 256>>>(ctx_out);
}

// round 5
// speedup vs baseline: 1.0951x; 1.0951x over previous
#include <cuda_runtime.h>
#include <math_constants.h>
#include <cstdint>

#define Bb 16
#define Ss 2048
#define Hh 1024
#define Mm (Bb * Ss)   // 32768

#define NCH 64           // context S-chunks
__device__ float g_q[Bb * Hh];
__device__ float g_ctx_part[16 * NCH * 1024];

// ---------------------------------------------------------------- helpers
__device__ __forceinline__ uint32_t smem_u32(const void* p) {
    uint32_t a;
    asm("{ .reg .u64 t; cvta.to.shared.u64 t, %1; cvt.u32.u64 %0, t; }" : "=r"(a) : "l"(p));
    return a;
}
__device__ __forceinline__ uint32_t f2tf(float f) {
    uint32_t u; asm("cvt.rna.tf32.f32 %0, %1;" : "=r"(u) : "f"(f)); return u;
}
__device__ __forceinline__ void cp_async16(uint32_t dst, const void* src) {
    asm volatile("cp.async.cg.shared.global [%0], [%1], 16;" :: "r"(dst), "l"(src));
}
__device__ __forceinline__ void cp_commit() { asm volatile("cp.async.commit_group;"); }
__device__ __forceinline__ void cp_wait1()  { asm volatile("cp.async.wait_group 1;"); }
__device__ __forceinline__ void cp_wait0()  { asm volatile("cp.async.wait_group 0;"); }

__device__ __forceinline__ void mma_tf32(float* d, const uint32_t* a, const uint32_t* b) {
    asm volatile(
        "mma.sync.aligned.m16n8k8.row.col.f32.tf32.tf32.f32 "
        "{%0,%1,%2,%3}, {%4,%5,%6,%7}, {%8,%9}, {%0,%1,%2,%3};"
        : "+f"(d[0]), "+f"(d[1]), "+f"(d[2]), "+f"(d[3])
        : "r"(a[0]), "r"(a[1]), "r"(a[2]), "r"(a[3]), "r"(b[0]), "r"(b[1]));
}

// ---------------------------------------------------------------------------
// Kernel 1: zero scores (grid.y==0 part) + q[b,o] = Wh.h_b + bias
// grid (Bb, Hh/8 + 2): y < Hh/8 computes q; last 2 y-slices zero scores
// ---------------------------------------------------------------------------
__global__ void q_zero_kernel(const float* __restrict__ h,
                              const float* __restrict__ W,
                              const float* __restrict__ bias,
                              float* __restrict__ scores) {
    int b = blockIdx.x;
    if (blockIdx.y >= Hh / 8) {
        int part = blockIdx.y - Hh / 8;          // 0..1
        scores[(size_t)b * Ss + part * 1024 + (threadIdx.x * 4) % 1024 +
               (threadIdx.x / 256) * 0] = 0.f;   // 256 threads cover 1024 via 4x
        int base = (size_t)b * Ss + part * 1024;
        for (int i = threadIdx.x; i < 1024; i += blockDim.x) scores[base + i] = 0.f;
        return;
    }
    __shared__ float hs[Hh];
    for (int i = threadIdx.x; i < Hh; i += blockDim.x) hs[i] = h[b * Hh + i];
    __syncthreads();
    int warp = threadIdx.x >> 5, lane = threadIdx.x & 31;
    int o = blockIdx.y * 8 + warp;
    const float* Wrow = W + (size_t)o * (2 * Hh);
    float acc = 0.f;
    #pragma unroll 8
    for (int k = lane; k < Hh; k += 32) acc += hs[k] * Wrow[k];
    #pragma unroll
    for (int off = 16; off; off >>= 1) acc += __shfl_xor_sync(0xffffffffu, acc, off);
    if (lane == 0) g_q[b * Hh + o] = acc + bias[o];
}

// ---------------------------------------------------------------------------
// Kernel 2: fused scores GEMM via tf32 mma.sync (m16n8k8) — R3 proven config.
// Grid (M/128, N/128). CTA tile 128x128, BK=16, cp.async double buffer.
// Smem tiles row-major padded to 20 floats/row (conflict-free fragment LDS).
// Epilogue: relu(+q)*v row-reduction in registers, atomicAdd row partials.
// ---------------------------------------------------------------------------
#define BKI 16
#define PAD 20
#define NIT (Hh / BKI)   // 64

__global__ void __launch_bounds__(256)
scores_mma(const float* __restrict__ A,
           const float* __restrict__ W,
           const float* __restrict__ v,
           float* __restrict__ out_scores) {
    __shared__ float As[2][128][PAD];
    __shared__ float Bs[2][128][PAD];
    __shared__ float s_q[128];
    __shared__ float s_v[128];

    const int tid  = threadIdx.x;
    const int wid  = tid >> 5, lane = tid & 31;
    const int g    = lane >> 2, t = lane & 3;
    const int bm   = blockIdx.x;          // m block (128 rows)
    const int bn   = blockIdx.y;          // n block (128 cols)
    const int b    = (bm * 128) >> 11;    // batch
    const int wm   = (wid & 3) * 32;      // warp m offset
    const int wn   = (wid >> 2) * 64;     // warp n offset

    if (tid < 128) {
        s_q[tid] = g_q[b * Hh + bn * 128 + tid];
        s_v[tid] = v[bn * 128 + tid];
    }

    const float* Agbase = A + (size_t)(bm * 128) * Hh;
    const float* Wgbase = W + (size_t)(bn * 128) * (2 * Hh) + Hh;

    const int r0 = tid >> 2, c0 = (tid & 3);          // rows 0..63
    const int r1 = r0 + 64;

    uint32_t sA[2][2], sB[2][2];
    #pragma unroll
    for (int s = 0; s < 2; s++) {
        sA[s][0] = smem_u32(&As[s][r0][c0 * 4]);
        sA[s][1] = smem_u32(&As[s][r1][c0 * 4]);
        sB[s][0] = smem_u32(&Bs[s][r0][c0 * 4]);
        sB[s][1] = smem_u32(&Bs[s][r1][c0 * 4]);
    }

    auto load_stage = [&](int s, int k0) {
        cp_async16(sA[s][0], Agbase + (size_t)r0 * Hh + k0 + c0 * 4);
        cp_async16(sA[s][1], Agbase + (size_t)r1 * Hh + k0 + c0 * 4);
        cp_async16(sB[s][0], Wgbase + (size_t)r0 * (2 * Hh) + k0 + c0 * 4);
        cp_async16(sB[s][1], Wgbase + (size_t)r1 * (2 * Hh) + k0 + c0 * 4);
        cp_commit();
    };

    float acc[2][8][4] = {};

    load_stage(0, 0);

    for (int it = 0; it < NIT; it++) {
        const int buf = it & 1;
        if (it + 1 < NIT) { load_stage(buf ^ 1, (it + 1) * BKI); cp_wait1(); }
        else              { cp_wait0(); }
        __syncthreads();

        #pragma unroll
        for (int ks = 0; ks < 2; ks++) {
            const int kb = ks * 8;
            uint32_t af[2][4];
            #pragma unroll
            for (int i = 0; i < 2; i++) {
                const int mr = wm + i * 16;
                af[i][0] = f2tf(As[buf][mr + g    ][kb + t    ]);
                af[i][1] = f2tf(As[buf][mr + g + 8][kb + t    ]);
                af[i][2] = f2tf(As[buf][mr + g    ][kb + t + 4]);
                af[i][3] = f2tf(As[buf][mr + g + 8][kb + t + 4]);
            }
            #pragma unroll
            for (int j = 0; j < 8; j++) {
                uint32_t bf[2];
                bf[0] = f2tf(Bs[buf][wn + j * 8 + g][kb + t    ]);
                bf[1] = f2tf(Bs[buf][wn + j * 8 + g][kb + t + 4]);
                mma_tf32(acc[0][j], af[0], bf);
                mma_tf32(acc[1][j], af[1], bf);
            }
        }
        __syncthreads();
    }

    // epilogue: relu(+q)*v, reduce cols
    float rs[2][2] = {};
    #pragma unroll
    for (int j = 0; j < 8; j++) {
        const int nl = wn + j * 8 + 2 * t;
        const float q0 = s_q[nl], q1 = s_q[nl + 1];
        const float v0 = s_v[nl], v1 = s_v[nl + 1];
        #pragma unroll
        for (int i = 0; i < 2; i++) {
            rs[i][0] += fmaxf(acc[i][j][0] + q0, 0.f) * v0 + fmaxf(acc[i][j][1] + q1, 0.f) * v1;
            rs[i][1] += fmaxf(acc[i][j][2] + q0, 0.f) * v0 + fmaxf(acc[i][j][3] + q1, 0.f) * v1;
        }
    }
    #pragma unroll
    for (int off = 1; off < 4; off <<= 1) {
        #pragma unroll
        for (int i = 0; i < 2; i++) {
            rs[i][0] += __shfl_xor_sync(0xffffffffu, rs[i][0], off);
            rs[i][1] += __shfl_xor_sync(0xffffffffu, rs[i][1], off);
        }
    }
    if (t == 0) {
        const int rowb = bm * 128 + wm;
        #pragma unroll
        for (int i = 0; i < 2; i++) {
            atomicAdd(&out_scores[rowb + i * 16 + g    ], rs[i][0]);
            atomicAdd(&out_scores[rowb + i * 16 + g + 8], rs[i][1]);
        }
    }
}

// ---------------------------------------------------------------------------
// Kernel 3: in-place softmax over S per batch
// ---------------------------------------------------------------------------
__global__ void softmax_kernel(float* __restrict__ w) {
    int b = blockIdx.x;
    float* row = w + (size_t)b * Ss;
    __shared__ float red[256];
    int tid = threadIdx.x;

    float m = -CUDART_INF_F;
    for (int i = tid; i < Ss; i += 256) m = fmaxf(m, row[i]);
    red[tid] = m; __syncthreads();
    for (int s = 128; s; s >>= 1) { if (tid < s) red[tid] = fmaxf(red[tid], red[tid + s]); __syncthreads(); }
    m = red[0]; __syncthreads();

    float sum = 0.f;
    for (int i = tid; i < Ss; i += 256) { float e = __expf(row[i] - m); row[i] = e; sum += e; }
    red[tid] = sum; __syncthreads();
    for (int s = 128; s; s >>= 1) { if (tid < s) red[tid] += red[tid + s]; __syncthreads(); }
    float inv = 1.f / red[0]; __syncthreads();
    for (int i = tid; i < Ss; i += 256) row[i] *= inv;
}

// ---------------------------------------------------------------------------
// Kernel 4a: context partials. grid (NCH schunks, B), block 256; 32 rows/chunk
// ---------------------------------------------------------------------------
__global__ void context_part_kernel(const float* __restrict__ A,
                                    const float* __restrict__ w) {
    int sc = blockIdx.x, b = blockIdx.y;
    __shared__ float ws[32];
    int tid = threadIdx.x;
    if (tid < 32) ws[tid] = w[(size_t)b * Ss + sc * 32 + tid];
    __syncthreads();
    int h4 = tid * 4;
    const float* Ab = A + ((size_t)b * Ss + sc * 32) * Hh + h4;
    float4 acc = {0.f, 0.f, 0.f, 0.f};
    #pragma unroll 8
    for (int s = 0; s < 32; s++) {
        float4 av = __ldg((const float4*)(Ab + (size_t)s * Hh));
        float wv = ws[s];
        acc.x += wv * av.x; acc.y += wv * av.y; acc.z += wv * av.z; acc.w += wv * av.w;
    }
    *(float4*)(g_ctx_part + ((size_t)(b * NCH + sc) * Hh) + h4) = acc;
}

// Kernel 4b: reduce partials
__global__ void context_reduce_kernel(float* __restrict__ ctx) {
    int b = blockIdx.x;
    int h4 = threadIdx.x * 4;
    float4 s = {0.f, 0.f, 0.f, 0.f};
    #pragma unroll
    for (int j = 0; j < NCH; j++) {
        float4 p = *(const float4*)(g_ctx_part + ((size_t)(b * NCH + j) * Hh) + h4);
        s.x += p.x; s.y += p.y; s.z += p.z; s.w += p.w;
    }
    *(float4*)(ctx + (size_t)b * Hh + h4) = s;
}

// ---------------------------------------------------------------------------
extern "C" void kernel_launch(void* const* d_in, const int* in_sizes, int n_in,
                              void* d_out, int out_size) {
    const float* h    = (const float*)d_in[0];
    // d_in[1] = c (unused)
    const float* a    = (const float*)d_in[2];
    const float* W    = (const float*)d_in[3];
    const float* bias = (const float*)d_in[4];
    const float* vW   = (const float*)d_in[5];

    float* ctx_out  = (float*)d_out;              // (B,1,H)
    float* attn_out = (float*)d_out + Bb * Hh;    // (B,S)

    q_zero_kernel<<<dim3(Bb, Hh / 8 + 2), 256>>>(h, W, bias, attn_out);
    scores_mma<<<dim3(Mm / 128, Hh / 128), 256>>>(a, W, vW, attn_out);
    softmax_kernel<<<Bb, 256>>>(attn_out);
    context_part_kernel<<<dim3(NCH, Bb), 256>>>(a, attn_out);
    context_reduce_kernel<<<Bb, 256>>>(ctx_out);
}

// round 6
// speedup vs baseline: 1.2554x; 1.1464x over previous
#include <cuda_runtime.h>
#include <math_constants.h>
#include <cstdint>

#define Bb 16
#define Ss 2048
#define Hh 1024
#define Mm (Bb * Ss)   // 32768

#define NCH 64           // context S-chunks
__device__ float g_q[Bb * Hh];
__device__ float g_ctx_part[16 * NCH * 1024];

// ---------------------------------------------------------------- helpers
__device__ __forceinline__ uint32_t smem_u32(const void* p) {
    uint32_t a;
    asm("{ .reg .u64 t; cvta.to.shared.u64 t, %1; cvt.u32.u64 %0, t; }" : "=r"(a) : "l"(p));
    return a;
}
__device__ __forceinline__ void cp_async16(uint32_t dst, const void* src) {
    asm volatile("cp.async.cg.shared.global [%0], [%1], 16;" :: "r"(dst), "l"(src));
}
__device__ __forceinline__ void cp_commit() { asm volatile("cp.async.commit_group;"); }
__device__ __forceinline__ void cp_wait1()  { asm volatile("cp.async.wait_group 1;"); }
__device__ __forceinline__ void cp_wait0()  { asm volatile("cp.async.wait_group 0;"); }

__device__ __forceinline__ void ldsm_x4(uint32_t* r, uint32_t addr) {
    asm volatile("ldmatrix.sync.aligned.m8n8.x4.shared.b16 {%0,%1,%2,%3}, [%4];"
                 : "=r"(r[0]), "=r"(r[1]), "=r"(r[2]), "=r"(r[3]) : "r"(addr));
}

// raw fp32 bits fed as tf32 (HW truncates low mantissa bits)
__device__ __forceinline__ void mma_tf32(float* d, const uint32_t* a, uint32_t b0, uint32_t b1) {
    asm volatile(
        "mma.sync.aligned.m16n8k8.row.col.f32.tf32.tf32.f32 "
        "{%0,%1,%2,%3}, {%4,%5,%6,%7}, {%8,%9}, {%0,%1,%2,%3};"
        : "+f"(d[0]), "+f"(d[1]), "+f"(d[2]), "+f"(d[3])
        : "r"(a[0]), "r"(a[1]), "r"(a[2]), "r"(a[3]), "r"(b0), "r"(b1));
}

// ---------------------------------------------------------------------------
// Kernel 1: zero scores (tail y-slices) + q[b,o] = Wh.h_b + bias
// ---------------------------------------------------------------------------
__global__ void q_zero_kernel(const float* __restrict__ h,
                              const float* __restrict__ W,
                              const float* __restrict__ bias,
                              float* __restrict__ scores) {
    int b = blockIdx.x;
    if (blockIdx.y >= Hh / 8) {
        int part = blockIdx.y - Hh / 8;          // 0..1
        size_t base = (size_t)b * Ss + part * 1024;
        for (int i = threadIdx.x; i < 1024; i += blockDim.x) scores[base + i] = 0.f;
        return;
    }
    __shared__ float hs[Hh];
    for (int i = threadIdx.x; i < Hh; i += blockDim.x) hs[i] = h[b * Hh + i];
    __syncthreads();
    int warp = threadIdx.x >> 5, lane = threadIdx.x & 31;
    int o = blockIdx.y * 8 + warp;
    const float* Wrow = W + (size_t)o * (2 * Hh);
    float acc = 0.f;
    #pragma unroll 8
    for (int k = lane; k < Hh; k += 32) acc += hs[k] * Wrow[k];
    #pragma unroll
    for (int off = 16; off; off >>= 1) acc += __shfl_xor_sync(0xffffffffu, acc, off);
    if (lane == 0) g_q[b * Hh + o] = acc + bias[o];
}

// ---------------------------------------------------------------------------
// Kernel 2: fused scores GEMM, tf32 mma.sync + ldmatrix fragments.
// Grid (M/128, N/128). CTA tile 128x128, BK=16, cp.async double buffer.
// PAD=20 rows: conflict-free for both cp.async stores and LDSM reads.
// Epilogue: relu(+q)*v row-reduction, atomicAdd row partials.
// ---------------------------------------------------------------------------
#define BKI 16
#define PAD 20
#define NIT (Hh / BKI)   // 64
#define TILE_B (128 * PAD * 4)   // bytes per tile buffer (10240)

__global__ void __launch_bounds__(256, 2)
scores_mma(const float* __restrict__ A,
           const float* __restrict__ W,
           const float* __restrict__ v,
           float* __restrict__ out_scores) {
    __shared__ float As[2][128][PAD];
    __shared__ float Bs[2][128][PAD];
    __shared__ float s_q[128];
    __shared__ float s_v[128];

    const int tid  = threadIdx.x;
    const int wid  = tid >> 5, lane = tid & 31;
    const int g    = lane >> 2, t = lane & 3;
    const int bm   = blockIdx.x;          // m block (128 rows)
    const int bn   = blockIdx.y;          // n block (128 cols)
    const int b    = (bm * 128) >> 11;    // batch
    const int wm   = (wid & 3) * 32;      // warp m offset
    const int wn   = (wid >> 2) * 64;     // warp n offset

    if (tid < 128) {
        s_q[tid] = g_q[b * Hh + bn * 128 + tid];
        s_v[tid] = v[bn * 128 + tid];
    }

    const float* Agbase = A + (size_t)(bm * 128) * Hh;
    const float* Wgbase = W + (size_t)(bn * 128) * (2 * Hh) + Hh;

    const int r0 = tid >> 2, c0 = (tid & 3);          // rows 0..63
    const int r1 = r0 + 64;

    uint32_t sA[2][2], sB[2][2];
    #pragma unroll
    for (int s = 0; s < 2; s++) {
        sA[s][0] = smem_u32(&As[s][r0][c0 * 4]);
        sA[s][1] = smem_u32(&As[s][r1][c0 * 4]);
        sB[s][0] = smem_u32(&Bs[s][r0][c0 * 4]);
        sB[s][1] = smem_u32(&Bs[s][r1][c0 * 4]);
    }

    // LDSM lane addressing: lanes 0-15 -> rows base+0..15 (k lo half),
    // lanes 16-31 -> rows base+0..15 (k hi half, +4 floats)
    const int rowsel = lane & 15;
    const int colsel = (lane >> 4) * 4;
    const uint32_t aAddr = smem_u32(&As[0][wm + rowsel][colsel]);
    const uint32_t bAddr = smem_u32(&Bs[0][wn + rowsel][colsel]);

    auto load_stage = [&](int s, int k0) {
        cp_async16(sA[s][0], Agbase + (size_t)r0 * Hh + k0 + c0 * 4);
        cp_async16(sA[s][1], Agbase + (size_t)r1 * Hh + k0 + c0 * 4);
        cp_async16(sB[s][0], Wgbase + (size_t)r0 * (2 * Hh) + k0 + c0 * 4);
        cp_async16(sB[s][1], Wgbase + (size_t)r1 * (2 * Hh) + k0 + c0 * 4);
        cp_commit();
    };

    float acc[2][8][4] = {};

    load_stage(0, 0);

    for (int it = 0; it < NIT; it++) {
        const int buf = it & 1;
        if (it + 1 < NIT) { load_stage(buf ^ 1, (it + 1) * BKI); cp_wait1(); }
        else              { cp_wait0(); }
        __syncthreads();

        const uint32_t aB = aAddr + buf * TILE_B;
        const uint32_t bB = bAddr + buf * TILE_B;

        #pragma unroll
        for (int ks = 0; ks < 2; ks++) {
            const uint32_t ko = ks * 32;           // 8 floats
            uint32_t a0[4], a1[4], b0[4], b1[4], b2[4], b3[4];
            // A: two 16-row m-tiles (rows wm+0..15, wm+16..31)
            ldsm_x4(a0, aB + ko);
            ldsm_x4(a1, aB + ko + 16 * PAD * 4);
            // B: four 16-row jj-groups (j = 2*jj, 2*jj+1)
            ldsm_x4(b0, bB + ko);
            ldsm_x4(b1, bB + ko + 16 * PAD * 4);
            ldsm_x4(b2, bB + ko + 32 * PAD * 4);
            ldsm_x4(b3, bB + ko + 48 * PAD * 4);

            // bq regs: [0]=j even (k lo), [1]=j odd (k lo), [2]=j even (k hi), [3]=j odd (k hi)
            mma_tf32(acc[0][0], a0, b0[0], b0[2]);  mma_tf32(acc[1][0], a1, b0[0], b0[2]);
            mma_tf32(acc[0][1], a0, b0[1], b0[3]);  mma_tf32(acc[1][1], a1, b0[1], b0[3]);
            mma_tf32(acc[0][2], a0, b1[0], b1[2]);  mma_tf32(acc[1][2], a1, b1[0], b1[2]);
            mma_tf32(acc[0][3], a0, b1[1], b1[3]);  mma_tf32(acc[1][3], a1, b1[1], b1[3]);
            mma_tf32(acc[0][4], a0, b2[0], b2[2]);  mma_tf32(acc[1][4], a1, b2[0], b2[2]);
            mma_tf32(acc[0][5], a0, b2[1], b2[3]);  mma_tf32(acc[1][5], a1, b2[1], b2[3]);
            mma_tf32(acc[0][6], a0, b3[0], b3[2]);  mma_tf32(acc[1][6], a1, b3[0], b3[2]);
            mma_tf32(acc[0][7], a0, b3[1], b3[3]);  mma_tf32(acc[1][7], a1, b3[1], b3[3]);
        }
        __syncthreads();
    }

    // epilogue: relu(+q)*v, reduce cols
    float rs[2][2] = {};
    #pragma unroll
    for (int j = 0; j < 8; j++) {
        const int nl = wn + j * 8 + 2 * t;
        const float q0 = s_q[nl], q1 = s_q[nl + 1];
        const float v0 = s_v[nl], v1 = s_v[nl + 1];
        #pragma unroll
        for (int i = 0; i < 2; i++) {
            rs[i][0] += fmaxf(acc[i][j][0] + q0, 0.f) * v0 + fmaxf(acc[i][j][1] + q1, 0.f) * v1;
            rs[i][1] += fmaxf(acc[i][j][2] + q0, 0.f) * v0 + fmaxf(acc[i][j][3] + q1, 0.f) * v1;
        }
    }
    #pragma unroll
    for (int off = 1; off < 4; off <<= 1) {
        #pragma unroll
        for (int i = 0; i < 2; i++) {
            rs[i][0] += __shfl_xor_sync(0xffffffffu, rs[i][0], off);
            rs[i][1] += __shfl_xor_sync(0xffffffffu, rs[i][1], off);
        }
    }
    if (t == 0) {
        const int rowb = bm * 128 + wm;
        #pragma unroll
        for (int i = 0; i < 2; i++) {
            atomicAdd(&out_scores[rowb + i * 16 + g    ], rs[i][0]);
            atomicAdd(&out_scores[rowb + i * 16 + g + 8], rs[i][1]);
        }
    }
}

// ---------------------------------------------------------------------------
// Kernel 3: in-place softmax over S per batch
// ---------------------------------------------------------------------------
__global__ void softmax_kernel(float* __restrict__ w) {
    int b = blockIdx.x;
    float* row = w + (size_t)b * Ss;
    __shared__ float red[256];
    int tid = threadIdx.x;

    float m = -CUDART_INF_F;
    for (int i = tid; i < Ss; i += 256) m = fmaxf(m, row[i]);
    red[tid] = m; __syncthreads();
    for (int s = 128; s; s >>= 1) { if (tid < s) red[tid] = fmaxf(red[tid], red[tid + s]); __syncthreads(); }
    m = red[0]; __syncthreads();

    float sum = 0.f;
    for (int i = tid; i < Ss; i += 256) { float e = __expf(row[i] - m); row[i] = e; sum += e; }
    red[tid] = sum; __syncthreads();
    for (int s = 128; s; s >>= 1) { if (tid < s) red[tid] += red[tid + s]; __syncthreads(); }
    float inv = 1.f / red[0]; __syncthreads();
    for (int i = tid; i < Ss; i += 256) row[i] *= inv;
}

// ---------------------------------------------------------------------------
// Kernel 4a: context partials. grid (NCH schunks, B), block 256; 32 rows/chunk
// ---------------------------------------------------------------------------
__global__ void context_part_kernel(const float* __restrict__ A,
                                    const float* __restrict__ w) {
    int sc = blockIdx.x, b = blockIdx.y;
    __shared__ float ws[32];
    int tid = threadIdx.x;
    if (tid < 32) ws[tid] = w[(size_t)b * Ss + sc * 32 + tid];
    __syncthreads();
    int h4 = tid * 4;
    const float* Ab = A + ((size_t)b * Ss + sc * 32) * Hh + h4;
    float4 acc = {0.f, 0.f, 0.f, 0.f};
    #pragma unroll 8
    for (int s = 0; s < 32; s++) {
        float4 av = __ldg((const float4*)(Ab + (size_t)s * Hh));
        float wv = ws[s];
        acc.x += wv * av.x; acc.y += wv * av.y; acc.z += wv * av.z; acc.w += wv * av.w;
    }
    *(float4*)(g_ctx_part + ((size_t)(b * NCH + sc) * Hh) + h4) = acc;
}

// Kernel 4b: reduce partials
__global__ void context_reduce_kernel(float* __restrict__ ctx) {
    int b = blockIdx.x;
    int h4 = threadIdx.x * 4;
    float4 s = {0.f, 0.f, 0.f, 0.f};
    #pragma unroll
    for (int j = 0; j < NCH; j++) {
        float4 p = *(const float4*)(g_ctx_part + ((size_t)(b * NCH + j) * Hh) + h4);
        s.x += p.x; s.y += p.y; s.z += p.z; s.w += p.w;
    }
    *(float4*)(ctx + (size_t)b * Hh + h4) = s;
}

// ---------------------------------------------------------------------------
extern "C" void kernel_launch(void* const* d_in, const int* in_sizes, int n_in,
                              void* d_out, int out_size) {
    const float* h    = (const float*)d_in[0];
    // d_in[1] = c (unused)
    const float* a    = (const float*)d_in[2];
    const float* W    = (const float*)d_in[3];
    const float* bias = (const float*)d_in[4];
    const float* vW   = (const float*)d_in[5];

    float* ctx_out  = (float*)d_out;              // (B,1,H)
    float* attn_out = (float*)d_out + Bb * Hh;    // (B,S)

    q_zero_kernel<<<dim3(Bb, Hh / 8 + 2), 256>>>(h, W, bias, attn_out);
    scores_mma<<<dim3(Mm / 128, Hh / 128), 256>>>(a, W, vW, attn_out);
    softmax_kernel<<<Bb, 256>>>(attn_out);
    context_part_kernel<<<dim3(NCH, Bb), 256>>>(a, attn_out);
    context_reduce_kernel<<<Bb, 256>>>(ctx_out);
}

// round 7
// speedup vs baseline: 1.3223x; 1.0533x over previous
#include <cuda_runtime.h>
#include <math_constants.h>
#include <cstdint>

#define Bb 16
#define Ss 2048
#define Hh 1024
#define Mm (Bb * Ss)   // 32768

#define NCH 64           // context S-chunks
__device__ float g_q[Bb * Hh];
__device__ float g_ctx_part[16 * NCH * 1024];

// ---------------------------------------------------------------- helpers
__device__ __forceinline__ uint32_t smem_u32(const void* p) {
    uint32_t a;
    asm("{ .reg .u64 t; cvta.to.shared.u64 t, %1; cvt.u32.u64 %0, t; }" : "=r"(a) : "l"(p));
    return a;
}
__device__ __forceinline__ void cp_async16(uint32_t dst, const void* src) {
    asm volatile("cp.async.cg.shared.global [%0], [%1], 16;" :: "r"(dst), "l"(src));
}
__device__ __forceinline__ void cp_commit() { asm volatile("cp.async.commit_group;"); }
__device__ __forceinline__ void cp_wait1()  { asm volatile("cp.async.wait_group 1;"); }
__device__ __forceinline__ void cp_wait0()  { asm volatile("cp.async.wait_group 0;"); }

__device__ __forceinline__ void ldsm_x4(uint32_t* r, uint32_t addr) {
    asm volatile("ldmatrix.sync.aligned.m8n8.x4.shared.b16 {%0,%1,%2,%3}, [%4];"
                 : "=r"(r[0]), "=r"(r[1]), "=r"(r[2]), "=r"(r[3]) : "r"(addr));
}

// raw fp32 bits fed as tf32 (HW truncates low mantissa bits)
__device__ __forceinline__ void mma_tf32(float* d, const uint32_t* a, uint32_t b0, uint32_t b1) {
    asm volatile(
        "mma.sync.aligned.m16n8k8.row.col.f32.tf32.tf32.f32 "
        "{%0,%1,%2,%3}, {%4,%5,%6,%7}, {%8,%9}, {%0,%1,%2,%3};"
        : "+f"(d[0]), "+f"(d[1]), "+f"(d[2]), "+f"(d[3])
        : "r"(a[0]), "r"(a[1]), "r"(a[2]), "r"(a[3]), "r"(b0), "r"(b1));
}

// ---------------------------------------------------------------------------
// Kernels 0a/0b: zero scores halves (also positions scores_mma as 4th launch
// so ncu profiles it)
// ---------------------------------------------------------------------------
__global__ void zero_half(float* __restrict__ s) {
    s[(size_t)blockIdx.x * 1024 + threadIdx.x] = 0.f;
}

// ---------------------------------------------------------------------------
// Kernel 1: q[b,o] = dot(h[b,:], attn_W[o, 0:H]) + attn_b[o]
// ---------------------------------------------------------------------------
__global__ void q_kernel(const float* __restrict__ h,
                         const float* __restrict__ W,
                         const float* __restrict__ bias) {
    int b = blockIdx.x;
    __shared__ float hs[Hh];
    for (int i = threadIdx.x; i < Hh; i += blockDim.x) hs[i] = h[b * Hh + i];
    __syncthreads();
    int warp = threadIdx.x >> 5, lane = threadIdx.x & 31;
    int o = blockIdx.y * 8 + warp;
    const float* Wrow = W + (size_t)o * (2 * Hh);
    float acc = 0.f;
    #pragma unroll 8
    for (int k = lane; k < Hh; k += 32) acc += hs[k] * Wrow[k];
    #pragma unroll
    for (int off = 16; off; off >>= 1) acc += __shfl_xor_sync(0xffffffffu, acc, off);
    if (lane == 0) g_q[b * Hh + o] = acc + bias[o];
}

// ---------------------------------------------------------------------------
// Kernel 2: fused scores GEMM, tf32 mma.sync + ldmatrix, BK=32 (half barriers).
// Grid (M/128, N/128). CTA tile 128x128, dynamic smem 2-stage double buffer.
// PAD2=36 row stride: conflict-free cp.async stores and LDSM reads.
// Epilogue: relu(+q)*v row-reduction, atomicAdd row partials.
// ---------------------------------------------------------------------------
#define BKI 32
#define PAD2 36
#define NIT (Hh / BKI)                 // 32
#define TILE_F (128 * PAD2)            // 4608 floats
#define STAGE_F (2 * TILE_F)           // A + B
#define SC_SMEM (2 * STAGE_F * 4)      // 73728 bytes

__global__ void __launch_bounds__(256, 2)
scores_mma(const float* __restrict__ A,
           const float* __restrict__ W,
           const float* __restrict__ v,
           float* __restrict__ out_scores) {
    extern __shared__ float sm[];
    __shared__ float s_q[128];
    __shared__ float s_v[128];

    const int tid  = threadIdx.x;
    const int wid  = tid >> 5, lane = tid & 31;
    const int g    = lane >> 2, t = lane & 3;
    const int bm   = blockIdx.x;          // m block (128 rows)
    const int bn   = blockIdx.y;          // n block (128 cols)
    const int b    = (bm * 128) >> 11;    // batch
    const int wm   = (wid & 3) * 32;      // warp m offset
    const int wn   = (wid >> 2) * 64;     // warp n offset

    if (tid < 128) {
        s_q[tid] = g_q[b * Hh + bn * 128 + tid];
        s_v[tid] = v[bn * 128 + tid];
    }

    const float* Agbase = A + (size_t)(bm * 128) * Hh;
    const float* Wgbase = W + (size_t)(bn * 128) * (2 * Hh) + Hh;

    // cp.async addressing: 1024 float4 per tile, 4 per thread
    int rowv[4], q4v[4];
    uint32_t aw[2][4], bw[2][4];
    #pragma unroll
    for (int i = 0; i < 4; i++) {
        int f = tid + i * 256;
        rowv[i] = f >> 3; q4v[i] = f & 7;
        #pragma unroll
        for (int s = 0; s < 2; s++) {
            uint32_t base = smem_u32(sm + s * STAGE_F);
            aw[s][i] = base + (rowv[i] * PAD2 + q4v[i] * 4) * 4;
            bw[s][i] = base + (TILE_F + rowv[i] * PAD2 + q4v[i] * 4) * 4;
        }
    }

    // LDSM lane addressing
    const int rowsel = lane & 15;
    const int colsel = (lane >> 4) * 4;
    const uint32_t aAddr = smem_u32(sm) + ((wm + rowsel) * PAD2 + colsel) * 4;
    const uint32_t bAddr = smem_u32(sm) + (TILE_F + (wn + rowsel) * PAD2 + colsel) * 4;

    auto load_stage = [&](int s, int k0) {
        #pragma unroll
        for (int i = 0; i < 4; i++)
            cp_async16(aw[s][i], Agbase + (size_t)rowv[i] * Hh + k0 + q4v[i] * 4);
        #pragma unroll
        for (int i = 0; i < 4; i++)
            cp_async16(bw[s][i], Wgbase + (size_t)rowv[i] * (2 * Hh) + k0 + q4v[i] * 4);
        cp_commit();
    };

    float acc[2][8][4] = {};

    load_stage(0, 0);

    for (int it = 0; it < NIT; it++) {
        const int buf = it & 1;
        if (it + 1 < NIT) { load_stage(buf ^ 1, (it + 1) * BKI); cp_wait1(); }
        else              { cp_wait0(); }
        __syncthreads();

        const uint32_t aB = aAddr + buf * (STAGE_F * 4);
        const uint32_t bB = bAddr + buf * (STAGE_F * 4);

        #pragma unroll
        for (int ks = 0; ks < 4; ks++) {
            const uint32_t ko = ks * 32;           // 8 floats per k-step
            uint32_t a0[4], a1[4], b0[4], b1[4], b2[4], b3[4];
            ldsm_x4(a0, aB + ko);
            ldsm_x4(a1, aB + ko + 16 * PAD2 * 4);
            ldsm_x4(b0, bB + ko);
            ldsm_x4(b1, bB + ko + 16 * PAD2 * 4);
            ldsm_x4(b2, bB + ko + 32 * PAD2 * 4);
            ldsm_x4(b3, bB + ko + 48 * PAD2 * 4);

            mma_tf32(acc[0][0], a0, b0[0], b0[2]);  mma_tf32(acc[1][0], a1, b0[0], b0[2]);
            mma_tf32(acc[0][1], a0, b0[1], b0[3]);  mma_tf32(acc[1][1], a1, b0[1], b0[3]);
            mma_tf32(acc[0][2], a0, b1[0], b1[2]);  mma_tf32(acc[1][2], a1, b1[0], b1[2]);
            mma_tf32(acc[0][3], a0, b1[1], b1[3]);  mma_tf32(acc[1][3], a1, b1[1], b1[3]);
            mma_tf32(acc[0][4], a0, b2[0], b2[2]);  mma_tf32(acc[1][4], a1, b2[0], b2[2]);
            mma_tf32(acc[0][5], a0, b2[1], b2[3]);  mma_tf32(acc[1][5], a1, b2[1], b2[3]);
            mma_tf32(acc[0][6], a0, b3[0], b3[2]);  mma_tf32(acc[1][6], a1, b3[0], b3[2]);
            mma_tf32(acc[0][7], a0, b3[1], b3[3]);  mma_tf32(acc[1][7], a1, b3[1], b3[3]);
        }
        __syncthreads();
    }

    // epilogue: relu(+q)*v, reduce cols
    float rs[2][2] = {};
    #pragma unroll
    for (int j = 0; j < 8; j++) {
        const int nl = wn + j * 8 + 2 * t;
        const float q0 = s_q[nl], q1 = s_q[nl + 1];
        const float v0 = s_v[nl], v1 = s_v[nl + 1];
        #pragma unroll
        for (int i = 0; i < 2; i++) {
            rs[i][0] += fmaxf(acc[i][j][0] + q0, 0.f) * v0 + fmaxf(acc[i][j][1] + q1, 0.f) * v1;
            rs[i][1] += fmaxf(acc[i][j][2] + q0, 0.f) * v0 + fmaxf(acc[i][j][3] + q1, 0.f) * v1;
        }
    }
    #pragma unroll
    for (int off = 1; off < 4; off <<= 1) {
        #pragma unroll
        for (int i = 0; i < 2; i++) {
            rs[i][0] += __shfl_xor_sync(0xffffffffu, rs[i][0], off);
            rs[i][1] += __shfl_xor_sync(0xffffffffu, rs[i][1], off);
        }
    }
    if (t == 0) {
        const int rowb = bm * 128 + wm;
        #pragma unroll
        for (int i = 0; i < 2; i++) {
            atomicAdd(&out_scores[rowb + i * 16 + g    ], rs[i][0]);
            atomicAdd(&out_scores[rowb + i * 16 + g + 8], rs[i][1]);
        }
    }
}

// ---------------------------------------------------------------------------
// Kernel 3: in-place softmax over S per batch
// ---------------------------------------------------------------------------
__global__ void softmax_kernel(float* __restrict__ w) {
    int b = blockIdx.x;
    float* row = w + (size_t)b * Ss;
    __shared__ float red[256];
    int tid = threadIdx.x;

    float m = -CUDART_INF_F;
    for (int i = tid; i < Ss; i += 256) m = fmaxf(m, row[i]);
    red[tid] = m; __syncthreads();
    for (int s = 128; s; s >>= 1) { if (tid < s) red[tid] = fmaxf(red[tid], red[tid + s]); __syncthreads(); }
    m = red[0]; __syncthreads();

    float sum = 0.f;
    for (int i = tid; i < Ss; i += 256) { float e = __expf(row[i] - m); row[i] = e; sum += e; }
    red[tid] = sum; __syncthreads();
    for (int s = 128; s; s >>= 1) { if (tid < s) red[tid] += red[tid + s]; __syncthreads(); }
    float inv = 1.f / red[0]; __syncthreads();
    for (int i = tid; i < Ss; i += 256) row[i] *= inv;
}

// ---------------------------------------------------------------------------
// Kernel 4a: context partials. grid (NCH schunks, B), block 256; 32 rows/chunk
// ---------------------------------------------------------------------------
__global__ void context_part_kernel(const float* __restrict__ A,
                                    const float* __restrict__ w) {
    int sc = blockIdx.x, b = blockIdx.y;
    __shared__ float ws[32];
    int tid = threadIdx.x;
    if (tid < 32) ws[tid] = w[(size_t)b * Ss + sc * 32 + tid];
    __syncthreads();
    int h4 = tid * 4;
    const float* Ab = A + ((size_t)b * Ss + sc * 32) * Hh + h4;
    float4 acc = {0.f, 0.f, 0.f, 0.f};
    #pragma unroll 8
    for (int s = 0; s < 32; s++) {
        float4 av = __ldg((const float4*)(Ab + (size_t)s * Hh));
        float wv = ws[s];
        acc.x += wv * av.x; acc.y += wv * av.y; acc.z += wv * av.z; acc.w += wv * av.w;
    }
    *(float4*)(g_ctx_part + ((size_t)(b * NCH + sc) * Hh) + h4) = acc;
}

// Kernel 4b: reduce partials
__global__ void context_reduce_kernel(float* __restrict__ ctx) {
    int b = blockIdx.x;
    int h4 = threadIdx.x * 4;
    float4 s = {0.f, 0.f, 0.f, 0.f};
    #pragma unroll
    for (int j = 0; j < NCH; j++) {
        float4 p = *(const float4*)(g_ctx_part + ((size_t)(b * NCH + j) * Hh) + h4);
        s.x += p.x; s.y += p.y; s.z += p.z; s.w += p.w;
    }
    *(float4*)(ctx + (size_t)b * Hh + h4) = s;
}

// ---------------------------------------------------------------------------
extern "C" void kernel_launch(void* const* d_in, const int* in_sizes, int n_in,
                              void* d_out, int out_size) {
    const float* h    = (const float*)d_in[0];
    // d_in[1] = c (unused)
    const float* a    = (const float*)d_in[2];
    const float* W    = (const float*)d_in[3];
    const float* bias = (const float*)d_in[4];
    const float* vW   = (const float*)d_in[5];

    float* ctx_out  = (float*)d_out;              // (B,1,H)
    float* attn_out = (float*)d_out + Bb * Hh;    // (B,S)

    static bool attr_set = false;
    if (!attr_set) {
        cudaFuncSetAttribute(scores_mma, cudaFuncAttributeMaxDynamicSharedMemorySize, SC_SMEM);
        attr_set = true;
    }

    // launches 1-3 (scores_mma must be 4th — that's the one ncu reports)
    zero_half<<<Mm / 2048, 1024>>>(attn_out);
    zero_half<<<Mm / 2048, 1024>>>(attn_out + Mm / 2);
    q_kernel<<<dim3(Bb, Hh / 8), 256>>>(h, W, bias);
    scores_mma<<<dim3(Mm / 128, Hh / 128), 256, SC_SMEM>>>(a, W, vW, attn_out);
    softmax_kernel<<<Bb, 256>>>(attn_out);
    context_part_kernel<<<dim3(NCH, Bb), 256>>>(a, attn_out);
    context_reduce_kernel<<<Bb, 256>>>(ctx_out);
}

// round 8
// speedup vs baseline: 1.3416x; 1.0146x over previous
#include <cuda_runtime.h>
#include <math_constants.h>
#include <cstdint>

#define Bb 16
#define Ss 2048
#define Hh 1024
#define Mm (Bb * Ss)   // 32768

#define NCH 64           // context S-chunks
__device__ float g_q[Bb * Hh];
__device__ float g_ctx_part[16 * NCH * 1024];

// ---------------------------------------------------------------- helpers
__device__ __forceinline__ uint32_t smem_u32(const void* p) {
    uint32_t a;
    asm("{ .reg .u64 t; cvta.to.shared.u64 t, %1; cvt.u32.u64 %0, t; }" : "=r"(a) : "l"(p));
    return a;
}
__device__ __forceinline__ void cp_async16(uint32_t dst, const void* src) {
    asm volatile("cp.async.cg.shared.global [%0], [%1], 16;" :: "r"(dst), "l"(src));
}
__device__ __forceinline__ void cp_commit() { asm volatile("cp.async.commit_group;"); }
__device__ __forceinline__ void cp_wait1()  { asm volatile("cp.async.wait_group 1;"); }
__device__ __forceinline__ void cp_wait0()  { asm volatile("cp.async.wait_group 0;"); }

__device__ __forceinline__ void ldsm_x4(uint32_t* r, uint32_t addr) {
    asm volatile("ldmatrix.sync.aligned.m8n8.x4.shared.b16 {%0,%1,%2,%3}, [%4];"
                 : "=r"(r[0]), "=r"(r[1]), "=r"(r[2]), "=r"(r[3]) : "r"(addr));
}

// raw fp32 bits fed as tf32 (HW truncates low mantissa bits)
__device__ __forceinline__ void mma_tf32(float* d, const uint32_t* a, uint32_t b0, uint32_t b1) {
    asm volatile(
        "mma.sync.aligned.m16n8k8.row.col.f32.tf32.tf32.f32 "
        "{%0,%1,%2,%3}, {%4,%5,%6,%7}, {%8,%9}, {%0,%1,%2,%3};"
        : "+f"(d[0]), "+f"(d[1]), "+f"(d[2]), "+f"(d[3])
        : "r"(a[0]), "r"(a[1]), "r"(a[2]), "r"(a[3]), "r"(b0), "r"(b1));
}

// ---------------------------------------------------------------------------
// Kernels 0a/0b: zero scores halves (positions scores_mma as 4th launch)
// ---------------------------------------------------------------------------
__global__ void zero_half(float* __restrict__ s) {
    s[(size_t)blockIdx.x * 1024 + threadIdx.x] = 0.f;
}

// ---------------------------------------------------------------------------
// Kernel 1: q[b,o] = dot(h[b,:], attn_W[o, 0:H]) + attn_b[o]
// ---------------------------------------------------------------------------
__global__ void q_kernel(const float* __restrict__ h,
                         const float* __restrict__ W,
                         const float* __restrict__ bias) {
    int b = blockIdx.x;
    __shared__ float hs[Hh];
    for (int i = threadIdx.x; i < Hh; i += blockDim.x) hs[i] = h[b * Hh + i];
    __syncthreads();
    int warp = threadIdx.x >> 5, lane = threadIdx.x & 31;
    int o = blockIdx.y * 8 + warp;
    const float* Wrow = W + (size_t)o * (2 * Hh);
    float acc = 0.f;
    #pragma unroll 8
    for (int k = lane; k < Hh; k += 32) acc += hs[k] * Wrow[k];
    #pragma unroll
    for (int off = 16; off; off >>= 1) acc += __shfl_xor_sync(0xffffffffu, acc, off);
    if (lane == 0) g_q[b * Hh + o] = acc + bias[o];
}

// ---------------------------------------------------------------------------
// Kernel 2: fused scores GEMM, tf32 mma.sync + ldmatrix.
// CTA = 128 threads (4 warps), tile 64x128, 4 CTAs/SM for latency hiding.
// BK=32, 2-stage cp.async, PAD2=36 conflict-free. Addressing = base + imm.
// Epilogue: relu(+q)*v row-reduction, atomicAdd row partials.
// ---------------------------------------------------------------------------
#define BKI 32
#define PAD2 36
#define NIT (Hh / BKI)                 // 32
#define TA_F (64 * PAD2)               // A tile floats (2304)
#define TB_F (128 * PAD2)              // B tile floats (4608)
#define STAGE_F (TA_F + TB_F)          // 6912
#define STAGE_B (STAGE_F * 4)          // 27648 bytes
#define SC_SMEM (2 * STAGE_B)          // 55296 bytes

__global__ void __launch_bounds__(128, 4)
scores_mma(const float* __restrict__ A,
           const float* __restrict__ W,
           const float* __restrict__ v,
           float* __restrict__ out_scores) {
    extern __shared__ float sm[];
    __shared__ float s_q[128];
    __shared__ float s_v[128];

    const int tid  = threadIdx.x;
    const int wid  = tid >> 5, lane = tid & 31;
    const int g    = lane >> 2, t = lane & 3;
    const int bm   = blockIdx.x;          // m block (64 rows) — fastest
    const int bn   = blockIdx.y;          // n block (128 cols)
    const int b    = (bm * 64) >> 11;     // batch
    const int wm   = (wid & 1) * 32;      // warp m offset
    const int wn   = (wid >> 1) * 64;     // warp n offset

    s_q[tid] = g_q[b * Hh + bn * 128 + tid];
    s_v[tid] = v[bn * 128 + tid];

    // per-thread cp.async bases: row = tid>>3 (+16 per i), q4 = tid&7
    const int rowt = tid >> 3, q4t = tid & 7;
    const float* aG = A + (size_t)(bm * 64 + rowt) * Hh + q4t * 4;
    const float* bG = W + (size_t)(bn * 128 + rowt) * (2 * Hh) + Hh + q4t * 4;
    const uint32_t smBase = smem_u32(sm);
    const uint32_t aSm = smBase + (rowt * PAD2 + q4t * 4) * 4;
    const uint32_t bSm = smBase + (TA_F + rowt * PAD2 + q4t * 4) * 4;

    // LDSM bases
    const int rowsel = lane & 15;
    const int colsel = (lane >> 4) * 4;
    const uint32_t aAddr = smBase + ((wm + rowsel) * PAD2 + colsel) * 4;
    const uint32_t bAddr = smBase + (TA_F + (wn + rowsel) * PAD2 + colsel) * 4;

    auto load_stage = [&](int s, int k0) {
        const uint32_t so = s * STAGE_B;
        const float* ag = aG + k0;
        const float* bg = bG + k0;
        #pragma unroll
        for (int i = 0; i < 4; i++)    // A: 64 rows
            cp_async16(aSm + so + i * (16 * PAD2 * 4), ag + (size_t)i * 16 * Hh);
        #pragma unroll
        for (int i = 0; i < 8; i++)    // B: 128 rows
            cp_async16(bSm + so + i * (16 * PAD2 * 4), bg + (size_t)i * 16 * (2 * Hh));
        cp_commit();
    };

    float acc[2][8][4] = {};

    load_stage(0, 0);

    for (int it = 0; it < NIT; it++) {
        const int buf = it & 1;
        if (it + 1 < NIT) { load_stage(buf ^ 1, (it + 1) * BKI); cp_wait1(); }
        else              { cp_wait0(); }
        __syncthreads();

        const uint32_t aB = aAddr + buf * STAGE_B;
        const uint32_t bB = bAddr + buf * STAGE_B;

        #pragma unroll
        for (int ks = 0; ks < 4; ks++) {
            const uint32_t ko = ks * 32;           // 8 floats per k-step
            uint32_t a0[4], a1[4], b0[4], b1[4], b2[4], b3[4];
            ldsm_x4(a0, aB + ko);
            ldsm_x4(a1, aB + ko + 16 * PAD2 * 4);
            ldsm_x4(b0, bB + ko);
            ldsm_x4(b1, bB + ko + 16 * PAD2 * 4);
            ldsm_x4(b2, bB + ko + 32 * PAD2 * 4);
            ldsm_x4(b3, bB + ko + 48 * PAD2 * 4);

            mma_tf32(acc[0][0], a0, b0[0], b0[2]);  mma_tf32(acc[1][0], a1, b0[0], b0[2]);
            mma_tf32(acc[0][1], a0, b0[1], b0[3]);  mma_tf32(acc[1][1], a1, b0[1], b0[3]);
            mma_tf32(acc[0][2], a0, b1[0], b1[2]);  mma_tf32(acc[1][2], a1, b1[0], b1[2]);
            mma_tf32(acc[0][3], a0, b1[1], b1[3]);  mma_tf32(acc[1][3], a1, b1[1], b1[3]);
            mma_tf32(acc[0][4], a0, b2[0], b2[2]);  mma_tf32(acc[1][4], a1, b2[0], b2[2]);
            mma_tf32(acc[0][5], a0, b2[1], b2[3]);  mma_tf32(acc[1][5], a1, b2[1], b2[3]);
            mma_tf32(acc[0][6], a0, b3[0], b3[2]);  mma_tf32(acc[1][6], a1, b3[0], b3[2]);
            mma_tf32(acc[0][7], a0, b3[1], b3[3]);  mma_tf32(acc[1][7], a1, b3[1], b3[3]);
        }
        __syncthreads();
    }

    // epilogue: relu(+q)*v, reduce cols
    float rs[2][2] = {};
    #pragma unroll
    for (int j = 0; j < 8; j++) {
        const int nl = wn + j * 8 + 2 * t;
        const float q0 = s_q[nl], q1 = s_q[nl + 1];
        const float v0 = s_v[nl], v1 = s_v[nl + 1];
        #pragma unroll
        for (int i = 0; i < 2; i++) {
            rs[i][0] += fmaxf(acc[i][j][0] + q0, 0.f) * v0 + fmaxf(acc[i][j][1] + q1, 0.f) * v1;
            rs[i][1] += fmaxf(acc[i][j][2] + q0, 0.f) * v0 + fmaxf(acc[i][j][3] + q1, 0.f) * v1;
        }
    }
    #pragma unroll
    for (int off = 1; off < 4; off <<= 1) {
        #pragma unroll
        for (int i = 0; i < 2; i++) {
            rs[i][0] += __shfl_xor_sync(0xffffffffu, rs[i][0], off);
            rs[i][1] += __shfl_xor_sync(0xffffffffu, rs[i][1], off);
        }
    }
    if (t == 0) {
        const int rowb = bm * 64 + wm;
        #pragma unroll
        for (int i = 0; i < 2; i++) {
            atomicAdd(&out_scores[rowb + i * 16 + g    ], rs[i][0]);
            atomicAdd(&out_scores[rowb + i * 16 + g + 8], rs[i][1]);
        }
    }
}

// ---------------------------------------------------------------------------
// Kernel 3: in-place softmax over S per batch
// ---------------------------------------------------------------------------
__global__ void softmax_kernel(float* __restrict__ w) {
    int b = blockIdx.x;
    float* row = w + (size_t)b * Ss;
    __shared__ float red[256];
    int tid = threadIdx.x;

    float m = -CUDART_INF_F;
    for (int i = tid; i < Ss; i += 256) m = fmaxf(m, row[i]);
    red[tid] = m; __syncthreads();
    for (int s = 128; s; s >>= 1) { if (tid < s) red[tid] = fmaxf(red[tid], red[tid + s]); __syncthreads(); }
    m = red[0]; __syncthreads();

    float sum = 0.f;
    for (int i = tid; i < Ss; i += 256) { float e = __expf(row[i] - m); row[i] = e; sum += e; }
    red[tid] = sum; __syncthreads();
    for (int s = 128; s; s >>= 1) { if (tid < s) red[tid] += red[tid + s]; __syncthreads(); }
    float inv = 1.f / red[0]; __syncthreads();
    for (int i = tid; i < Ss; i += 256) row[i] *= inv;
}

// ---------------------------------------------------------------------------
// Kernel 4a: context partials. grid (NCH schunks, B), block 256; 32 rows/chunk
// ---------------------------------------------------------------------------
__global__ void context_part_kernel(const float* __restrict__ A,
                                    const float* __restrict__ w) {
    int sc = blockIdx.x, b = blockIdx.y;
    __shared__ float ws[32];
    int tid = threadIdx.x;
    if (tid < 32) ws[tid] = w[(size_t)b * Ss + sc * 32 + tid];
    __syncthreads();
    int h4 = tid * 4;
    const float* Ab = A + ((size_t)b * Ss + sc * 32) * Hh + h4;
    float4 acc = {0.f, 0.f, 0.f, 0.f};
    #pragma unroll 8
    for (int s = 0; s < 32; s++) {
        float4 av = __ldg((const float4*)(Ab + (size_t)s * Hh));
        float wv = ws[s];
        acc.x += wv * av.x; acc.y += wv * av.y; acc.z += wv * av.z; acc.w += wv * av.w;
    }
    *(float4*)(g_ctx_part + ((size_t)(b * NCH + sc) * Hh) + h4) = acc;
}

// Kernel 4b: reduce partials
__global__ void context_reduce_kernel(float* __restrict__ ctx) {
    int b = blockIdx.x;
    int h4 = threadIdx.x * 4;
    float4 s = {0.f, 0.f, 0.f, 0.f};
    #pragma unroll
    for (int j = 0; j < NCH; j++) {
        float4 p = *(const float4*)(g_ctx_part + ((size_t)(b * NCH + j) * Hh) + h4);
        s.x += p.x; s.y += p.y; s.z += p.z; s.w += p.w;
    }
    *(float4*)(ctx + (size_t)b * Hh + h4) = s;
}

// ---------------------------------------------------------------------------
extern "C" void kernel_launch(void* const* d_in, const int* in_sizes, int n_in,
                              void* d_out, int out_size) {
    const float* h    = (const float*)d_in[0];
    // d_in[1] = c (unused)
    const float* a    = (const float*)d_in[2];
    const float* W    = (const float*)d_in[3];
    const float* bias = (const float*)d_in[4];
    const float* vW   = (const float*)d_in[5];

    float* ctx_out  = (float*)d_out;              // (B,1,H)
    float* attn_out = (float*)d_out + Bb * Hh;    // (B,S)

    static bool attr_set = false;
    if (!attr_set) {
        cudaFuncSetAttribute(scores_mma, cudaFuncAttributeMaxDynamicSharedMemorySize, SC_SMEM);
        attr_set = true;
    }

    // launches 1-3 (scores_mma must be 4th — that's the one ncu reports)
    zero_half<<<Mm / 2048, 1024>>>(attn_out);
    zero_half<<<Mm / 2048, 1024>>>(attn_out + Mm / 2);
    q_kernel<<<dim3(Bb, Hh / 8), 256>>>(h, W, bias);
    scores_mma<<<dim3(Mm / 64, Hh / 128), 128, SC_SMEM>>>(a, W, vW, attn_out);
    softmax_kernel<<<Bb, 256>>>(attn_out);
    context_part_kernel<<<dim3(NCH, Bb), 256>>>(a, attn_out);
    context_reduce_kernel<<<Bb, 256>>>(ctx_out);
}